// round 2
// baseline (speedup 1.0000x reference)
#include <cuda_runtime.h>
#include <cuda_bf16.h>
#include <cstdint>

// ======================= problem sizes (fixed by dataset) ====================
#define TOKENS 4096
#define IC     4096
#define OC     4096
#define NOUTP  256   // outlier columns padded 204 -> 256

// ======================= device scratch (no runtime alloc) ==================
__device__ __nv_bfloat16 g_xhi[(size_t)TOKENS * IC];   // 32 MB
__device__ __nv_bfloat16 g_xlo[(size_t)TOKENS * IC];   // 32 MB
__device__ __nv_bfloat16 g_ws [(size_t)OC * IC];       // 32 MB  sign matrix (outlier cols zeroed)
__device__ __nv_bfloat16 g_xoh[(size_t)TOKENS * NOUTP];
__device__ __nv_bfloat16 g_xol[(size_t)TOKENS * NOUTP];
__device__ __nv_bfloat16 g_owh[(size_t)OC * NOUTP];    // (ow / s_o) hi
__device__ __nv_bfloat16 g_owl[(size_t)OC * NOUTP];    // (ow / s_o) lo
__device__ float g_mean[OC];
__device__ float g_scale[OC];   // effective scale (0 -> 1; exact, since then sign==0)
__device__ int   g_map[IC];

// ======================= helpers =============================================
__device__ __forceinline__ uint32_t smem_u32(const void* p) {
    uint32_t a;
    asm("{ .reg .u64 t; cvta.to.shared.u64 t, %1; cvt.u32.u64 %0, t; }"
        : "=r"(a) : "l"(p));
    return a;
}

#define CP_ASYNC16(saddr, gaddr) \
    asm volatile("cp.async.cg.shared.global [%0], [%1], 16;" \
                 :: "r"(saddr), "l"(gaddr))
#define CP_COMMIT() asm volatile("cp.async.commit_group;" ::: "memory")
#define CP_WAIT2()  asm volatile("cp.async.wait_group 2;" ::: "memory")

#define LDMATRIX_X4(r0, r1, r2, r3, addr) \
    asm volatile("ldmatrix.sync.aligned.m8n8.x4.shared.b16 {%0,%1,%2,%3}, [%4];" \
                 : "=r"(r0), "=r"(r1), "=r"(r2), "=r"(r3) : "r"(addr))

#define MMA16816(d, a, b0, b1) \
    asm volatile("mma.sync.aligned.m16n8k16.row.col.f32.bf16.bf16.f32 " \
                 "{%0,%1,%2,%3}, {%4,%5,%6,%7}, {%8,%9}, {%0,%1,%2,%3};" \
                 : "+f"((d)[0]), "+f"((d)[1]), "+f"((d)[2]), "+f"((d)[3]) \
                 : "r"((a)[0]), "r"((a)[1]), "r"((a)[2]), "r"((a)[3]), \
                   "r"(b0), "r"(b1))

// ======================= prep kernels ========================================
__global__ void row_stats_kernel(const float* __restrict__ w) {
    __shared__ float red[256];
    int o = blockIdx.x;
    const float* row = w + (size_t)o * IC;
    float s = 0.f;
    for (int i = threadIdx.x; i < IC; i += 256) s += row[i];
    red[threadIdx.x] = s;
    __syncthreads();
    for (int st = 128; st > 0; st >>= 1) {
        if (threadIdx.x < st) red[threadIdx.x] += red[threadIdx.x + st];
        __syncthreads();
    }
    float mean = red[0] * (1.0f / IC);
    __syncthreads();
    float a = 0.f;
    for (int i = threadIdx.x; i < IC; i += 256) a += fabsf(row[i] - mean);
    red[threadIdx.x] = a;
    __syncthreads();
    for (int st = 128; st > 0; st >>= 1) {
        if (threadIdx.x < st) red[threadIdx.x] += red[threadIdx.x + st];
        __syncthreads();
    }
    if (threadIdx.x == 0) {
        g_mean[o] = mean;
        float sc = red[0] * (1.0f / IC);
        g_scale[o] = (sc == 0.f) ? 1.f : sc;  // sc==0 => whole row sign==0, so 1 is exact
    }
}

__global__ void map_init_kernel() {
    int i = blockIdx.x * 256 + threadIdx.x;
    if (i < IC) g_map[i] = -1;
}

__global__ void map_scatter_kernel(const int* __restrict__ idx, int nout) {
    int j = blockIdx.x * 256 + threadIdx.x;
    if (j < nout) g_map[idx[j]] = j;
}

// sign matrix, outlier cols zeroed (exact in bf16: -1, 0, +1)
__global__ void build_ws_kernel(const float* __restrict__ w) {
    size_t t = (size_t)blockIdx.x * 256 + threadIdx.x;
    if (t >= (size_t)OC * IC) return;
    int o = (int)(t >> 12);       // /IC
    int i = (int)(t & (IC - 1));
    float v;
    if (g_map[i] >= 0) {
        v = 0.f;
    } else {
        float wc = w[t] - g_mean[o];
        v = (wc > 0.f) ? 1.f : ((wc < 0.f) ? -1.f : 0.f);
    }
    g_ws[t] = __float2bfloat16(v);
}

// x split hi/lo
__global__ void build_x_kernel(const float* __restrict__ x) {
    size_t t = (size_t)blockIdx.x * 256 + threadIdx.x;
    if (t >= (size_t)TOKENS * IC) return;
    float xv = x[t];
    __nv_bfloat16 hi = __float2bfloat16(xv);
    g_xhi[t] = hi;
    g_xlo[t] = __float2bfloat16(xv - __bfloat162float(hi));
}

// gathered outlier x columns, split hi/lo, padded with zeros
__global__ void build_xout_kernel(const float* __restrict__ x,
                                  const int* __restrict__ idx, int nout) {
    size_t t = (size_t)blockIdx.x * 256 + threadIdx.x;
    if (t >= (size_t)TOKENS * NOUTP) return;
    int tok = (int)(t >> 8);
    int j = (int)(t & (NOUTP - 1));
    float v = 0.f;
    if (j < nout) v = x[(size_t)tok * IC + idx[j]];
    __nv_bfloat16 hi = __float2bfloat16(v);
    g_xoh[t] = hi;
    g_xol[t] = __float2bfloat16(v - __bfloat162float(hi));
}

// outlier weights pre-divided by s_o, split hi/lo, padded with zeros
__global__ void build_ow_kernel(const float* __restrict__ ow, int nout) {
    size_t t = (size_t)blockIdx.x * 256 + threadIdx.x;
    if (t >= (size_t)OC * NOUTP) return;
    int o = (int)(t >> 8);
    int j = (int)(t & (NOUTP - 1));
    float v = 0.f;
    if (j < nout) v = ow[(size_t)o * nout + j] / g_scale[o];
    __nv_bfloat16 hi = __float2bfloat16(v);
    g_owh[t] = hi;
    g_owl[t] = __float2bfloat16(v - __bfloat162float(hi));
}

// ======================= main GEMM ===========================================
// CTA tile: 128 (tokens) x 256 (out-ch), BK=64 bf16. 256 threads = 8 warps
// in a 2(m) x 4(n) grid; warp tile 64x64 via mma.m16n8k16 bf16.
// Each K-tile carries TWO A tiles (hi & lo) sharing one B tile:
//   kt 0..63 : A1=xhi, A2=xlo, B=sign          (K = 4096 binary part)
//   kt 64..67: A1=xoh, A2=xol, B=owh           (outlier, hi weights)
//   kt 68..71: A1=xoh, A2=xol, B=owl           (outlier, lo weights)
// Epilogue: out = acc * s_o + bias.
static constexpr int BM = 128, BN = 256, BK = 64;
static constexpr int NT = 72;
static constexpr int STAGE_BYTES = (2 * BM + BN) * BK * 2;  // 65536
static constexpr int OFF_A2 = BM * BK * 2;                   // 16384
static constexpr int OFF_B  = 2 * BM * BK * 2;               // 32768
static constexpr int SMEM_BYTES = 3 * STAGE_BYTES;           // 196608

__global__ void __launch_bounds__(256, 1)
gemm_kernel(float* __restrict__ out, const float* __restrict__ bias) {
    extern __shared__ __align__(1024) char smem[];
    const uint32_t sbase = smem_u32(smem);
    const int tid = threadIdx.x;
    const int bn = blockIdx.x, bm = blockIdx.y;
    const int wid = tid >> 5, lane = tid & 31;
    const int wm = wid >> 2, wn = wid & 3;

    float acc[4][8][4];
#pragma unroll
    for (int i = 0; i < 4; ++i)
#pragma unroll
        for (int j = 0; j < 8; ++j)
#pragma unroll
            for (int k = 0; k < 4; ++k) acc[i][j][k] = 0.f;

    // ---- stage loader --------------------------------------------------
    auto issue = [&](int kt, int s) {
        const __nv_bfloat16 *a1, *a2, *b;
        int stride;
        if (kt < 64) {
            int off = kt * 64;
            a1 = g_xhi + (size_t)bm * BM * IC + off;
            a2 = g_xlo + (size_t)bm * BM * IC + off;
            b  = g_ws  + (size_t)bn * BN * IC + off;
            stride = IC;
        } else {
            int t = kt - 64;
            int off = (t & 3) * 64;
            a1 = g_xoh + (size_t)bm * BM * NOUTP + off;
            a2 = g_xol + (size_t)bm * BM * NOUTP + off;
            b  = ((t >> 2) ? g_owl : g_owh) + (size_t)bn * BN * NOUTP + off;
            stride = NOUTP;
        }
        uint32_t st = sbase + s * STAGE_BYTES;
#pragma unroll
        for (int i = 0; i < 4; ++i) {
            int c = tid + i * 256;
            int row = c >> 3, ch = c & 7;
            uint32_t so = (uint32_t)row * 128 + (uint32_t)((ch ^ (row & 7)) << 4);
            CP_ASYNC16(st + so, a1 + (size_t)row * stride + ch * 8);
            CP_ASYNC16(st + OFF_A2 + so, a2 + (size_t)row * stride + ch * 8);
        }
#pragma unroll
        for (int i = 0; i < 8; ++i) {
            int c = tid + i * 256;
            int row = c >> 3, ch = c & 7;
            uint32_t so = (uint32_t)row * 128 + (uint32_t)((ch ^ (row & 7)) << 4);
            CP_ASYNC16(st + OFF_B + so, b + (size_t)row * stride + ch * 8);
        }
    };

    // ---- compute on one stage ------------------------------------------
    auto compute = [&](int s) {
        uint32_t stA1 = sbase + s * STAGE_BYTES;
        uint32_t stA2 = stA1 + OFF_A2;
        uint32_t stB  = stA1 + OFF_B;
#pragma unroll
        for (int ks = 0; ks < 4; ++ks) {
            uint32_t bfr[4][4];
#pragma unroll
            for (int nj = 0; nj < 4; ++nj) {
                int row = wn * 64 + nj * 16 + (lane & 7) + (((lane >> 4) & 1) << 3);
                int ch = ks * 2 + ((lane >> 3) & 1);
                uint32_t ad = stB + (uint32_t)row * 128 + (uint32_t)((ch ^ (row & 7)) << 4);
                LDMATRIX_X4(bfr[nj][0], bfr[nj][1], bfr[nj][2], bfr[nj][3], ad);
            }
            uint32_t afr[4][4];
#pragma unroll
            for (int mi = 0; mi < 4; ++mi) {
                int row = wm * 64 + mi * 16 + (lane & 15);
                int ch = ks * 2 + (lane >> 4);
                uint32_t ad = stA1 + (uint32_t)row * 128 + (uint32_t)((ch ^ (row & 7)) << 4);
                LDMATRIX_X4(afr[mi][0], afr[mi][1], afr[mi][2], afr[mi][3], ad);
            }
#pragma unroll
            for (int mi = 0; mi < 4; ++mi)
#pragma unroll
                for (int nf = 0; nf < 8; ++nf)
                    MMA16816(acc[mi][nf], afr[mi],
                             bfr[nf >> 1][(nf & 1) * 2], bfr[nf >> 1][(nf & 1) * 2 + 1]);
#pragma unroll
            for (int mi = 0; mi < 4; ++mi) {
                int row = wm * 64 + mi * 16 + (lane & 15);
                int ch = ks * 2 + (lane >> 4);
                uint32_t ad = stA2 + (uint32_t)row * 128 + (uint32_t)((ch ^ (row & 7)) << 4);
                LDMATRIX_X4(afr[mi][0], afr[mi][1], afr[mi][2], afr[mi][3], ad);
            }
#pragma unroll
            for (int mi = 0; mi < 4; ++mi)
#pragma unroll
                for (int nf = 0; nf < 8; ++nf)
                    MMA16816(acc[mi][nf], afr[mi],
                             bfr[nf >> 1][(nf & 1) * 2], bfr[nf >> 1][(nf & 1) * 2 + 1]);
        }
    };

    // ---- pipelined main loop -------------------------------------------
    issue(0, 0); CP_COMMIT();
    issue(1, 1); CP_COMMIT();
    for (int kt = 0; kt < NT; ++kt) {
        if (kt + 2 < NT) issue(kt + 2, (kt + 2) % 3);
        CP_COMMIT();
        CP_WAIT2();
        __syncthreads();
        compute(kt % 3);
        __syncthreads();
    }

    // ---- epilogue: out = acc * s_o + bias ------------------------------
#pragma unroll
    for (int nf = 0; nf < 8; ++nf) {
        int col = bn * BN + wn * 64 + nf * 8 + 2 * (lane & 3);
        float s0 = g_scale[col], s1 = g_scale[col + 1];
        float b0 = __ldg(bias + col), b1 = __ldg(bias + col + 1);
#pragma unroll
        for (int mi = 0; mi < 4; ++mi) {
            int r0 = bm * BM + wm * 64 + mi * 16 + (lane >> 2);
            float2 v0 = make_float2(acc[mi][nf][0] * s0 + b0,
                                    acc[mi][nf][1] * s1 + b1);
            *(float2*)(out + (size_t)r0 * OC + col) = v0;
            float2 v1 = make_float2(acc[mi][nf][2] * s0 + b0,
                                    acc[mi][nf][3] * s1 + b1);
            *(float2*)(out + (size_t)(r0 + 8) * OC + col) = v1;
        }
    }
}

// ======================= launcher ============================================
extern "C" void kernel_launch(void* const* d_in, const int* in_sizes, int n_in,
                              void* d_out, int out_size) {
    const float* x = (const float*)d_in[0];
    const float* w = (const float*)d_in[1];
    const float* bias = (const float*)d_in[2];
    const float* ow = (const float*)d_in[3];
    const int* idx = (const int*)d_in[4];
    float* out = (float*)d_out;
    int nout = in_sizes[4];

    static bool attr_set = false;
    if (!attr_set) {
        cudaFuncSetAttribute(gemm_kernel,
                             cudaFuncAttributeMaxDynamicSharedMemorySize, SMEM_BYTES);
        attr_set = true;
    }

    row_stats_kernel<<<OC, 256>>>(w);
    map_init_kernel<<<(IC + 255) / 256, 256>>>();
    map_scatter_kernel<<<(nout + 255) / 256, 256>>>(idx, nout);
    build_ws_kernel<<<(unsigned)(((size_t)OC * IC + 255) / 256), 256>>>(w);
    build_x_kernel<<<(unsigned)(((size_t)TOKENS * IC + 255) / 256), 256>>>(x);
    build_xout_kernel<<<(unsigned)(((size_t)TOKENS * NOUTP + 255) / 256), 256>>>(x, idx, nout);
    build_ow_kernel<<<(unsigned)(((size_t)OC * NOUTP + 255) / 256), 256>>>(ow, nout);

    dim3 grid(OC / BN, TOKENS / BM);
    gemm_kernel<<<grid, 256, SMEM_BYTES>>>(out, bias);
}